// round 6
// baseline (speedup 1.0000x reference)
#include <cuda_runtime.h>
#include <cuda_bf16.h>
#include <math.h>
#include <stdint.h>

// ---------------- problem constants ----------------
#define T_TOK 16384      // BATCH * SEQ
#define D_IN  1024
#define D_OUT 1024
#define N_EXP 8
#define RANK  32
#define ER    256        // N_EXP * RANK
#define NCAT  1280       // D_OUT + ER

// ---------------- device scratch (static; no allocations) ----------------
__device__ __nv_bfloat16 g_Whi[NCAT * D_IN];   // [W ; A*sig(S_a)] hi
__device__ __nv_bfloat16 g_Wlo[NCAT * D_IN];   // lo residual (base rows used; A rows unused)
__device__ __nv_bfloat16 g_Bh [D_OUT * ER];    // B*sig(S_b) bf16, [o][e*R+r]
__device__ __nv_bfloat16 g_Xhi[T_TOK * D_IN];
__device__ __nv_bfloat16 g_Xlo[T_TOK * D_IN];
__device__ __nv_bfloat16 g_H  [T_TOK * ER];    // gated low-rank activations (bf16)
__device__ float         g_gate[T_TOK * N_EXP];

// ---------------- PTX helpers (sm_80-baseline ISA only) ----------------
__device__ __forceinline__ uint32_t smem_u32(const void* p) {
    uint32_t a;
    asm("{ .reg .u64 t; cvta.to.shared.u64 t, %1; cvt.u32.u64 %0, t; }"
        : "=r"(a) : "l"(p));
    return a;
}

__device__ __forceinline__ void cp16(uint32_t s, const void* g) {
    asm volatile("cp.async.cg.shared.global [%0], [%1], 16;" :: "r"(s), "l"(g) : "memory");
}
#define CP_COMMIT() asm volatile("cp.async.commit_group;" ::: "memory")
#define CP_WAIT1()  asm volatile("cp.async.wait_group 1;" ::: "memory")

__device__ __forceinline__ void ldsm4(uint32_t* r, uint32_t addr) {
    asm volatile("ldmatrix.sync.aligned.m8n8.x4.shared.b16 {%0,%1,%2,%3}, [%4];"
                 : "=r"(r[0]), "=r"(r[1]), "=r"(r[2]), "=r"(r[3]) : "r"(addr));
}

__device__ __forceinline__ void mma_bf16(float* c, const uint32_t* a, const uint32_t* b) {
    asm volatile(
        "mma.sync.aligned.m16n8k16.row.col.f32.bf16.bf16.f32 "
        "{%0,%1,%2,%3}, {%4,%5,%6,%7}, {%8,%9}, {%0,%1,%2,%3};"
        : "+f"(c[0]), "+f"(c[1]), "+f"(c[2]), "+f"(c[3])
        : "r"(a[0]), "r"(a[1]), "r"(a[2]), "r"(a[3]), "r"(b[0]), "r"(b[1]));
}

// ---------------- prep: weights -> bf16 (hi/lo for W, hi for Bcat) ----------------
__global__ void prep_kernel(const float* __restrict__ base_W,
                            const float* __restrict__ A,
                            const float* __restrict__ S_a,
                            const float* __restrict__ B,
                            const float* __restrict__ S_b) {
    const int totalW = D_OUT * D_IN;           // 1048576
    const int totalA = ER * D_IN;              // 262144
    const int totalB = N_EXP * D_OUT * RANK;   // 262144
    const int total  = totalW + totalA + totalB;
    for (int idx = blockIdx.x * blockDim.x + threadIdx.x; idx < total;
         idx += gridDim.x * blockDim.x) {
        if (idx < totalW) {
            float v = base_W[idx];
            __nv_bfloat16 h = __float2bfloat16_rn(v);
            g_Whi[idx] = h;
            g_Wlo[idx] = __float2bfloat16_rn(v - __bfloat162float(h));
        } else if (idx < totalW + totalA) {
            int i = idx - totalW;              // A is [E,R,D_IN]: row (e*R+r), col d
            float s = S_a[i];
            float v = A[i] * (1.0f / (1.0f + expf(-s)));
            __nv_bfloat16 h = __float2bfloat16_rn(v);
            g_Whi[totalW + i] = h;
            g_Wlo[totalW + i] = __float2bfloat16_rn(v - __bfloat162float(h));
        } else {
            int i = idx - totalW - totalA;     // B is [E, D_OUT, R]
            int e   = i / (D_OUT * RANK);
            int rem = i - e * (D_OUT * RANK);
            int o   = rem / RANK;
            int r   = rem - o * RANK;
            float s = S_b[i];
            float v = B[i] * (1.0f / (1.0f + expf(-s)));
            g_Bh[o * ER + e * RANK + r] = __float2bfloat16_rn(v);
        }
    }
}

// ---------------- router + X conversion fused ----------------
__global__ void router_kernel(const float4* __restrict__ x4,
                              const float4* __restrict__ rw4,
                              const float* __restrict__ router_b) {
    const int warp = (blockIdx.x * blockDim.x + threadIdx.x) >> 5;
    const int lane = threadIdx.x & 31;
    if (warp >= T_TOK) return;

    float acc[N_EXP];
#pragma unroll
    for (int e = 0; e < N_EXP; e++) acc[e] = 0.0f;

    const float4* xrow = x4 + (size_t)warp * (D_IN / 4);
    __nv_bfloat162* xh2 = (__nv_bfloat162*)(g_Xhi + (size_t)warp * D_IN);
    __nv_bfloat162* xl2 = (__nv_bfloat162*)(g_Xlo + (size_t)warp * D_IN);
#pragma unroll 2
    for (int j = lane; j < D_IN / 4; j += 32) {
        float4 xv = xrow[j];
#pragma unroll
        for (int e = 0; e < N_EXP; e++) {
            float4 wv = rw4[e * (D_IN / 4) + j];
            acc[e] += xv.x * wv.x + xv.y * wv.y + xv.z * wv.z + xv.w * wv.w;
        }
        __nv_bfloat16 h0 = __float2bfloat16_rn(xv.x);
        __nv_bfloat16 h1 = __float2bfloat16_rn(xv.y);
        __nv_bfloat16 h2 = __float2bfloat16_rn(xv.z);
        __nv_bfloat16 h3 = __float2bfloat16_rn(xv.w);
        xh2[2 * j]     = __halves2bfloat162(h0, h1);
        xh2[2 * j + 1] = __halves2bfloat162(h2, h3);
        xl2[2 * j]     = __halves2bfloat162(
            __float2bfloat16_rn(xv.x - __bfloat162float(h0)),
            __float2bfloat16_rn(xv.y - __bfloat162float(h1)));
        xl2[2 * j + 1] = __halves2bfloat162(
            __float2bfloat16_rn(xv.z - __bfloat162float(h2)),
            __float2bfloat16_rn(xv.w - __bfloat162float(h3)));
    }
#pragma unroll
    for (int e = 0; e < N_EXP; e++) {
#pragma unroll
        for (int off = 16; off; off >>= 1)
            acc[e] += __shfl_xor_sync(0xffffffffu, acc[e], off);
        acc[e] += router_b[e];
    }

    float mx = acc[0];
#pragma unroll
    for (int e = 1; e < N_EXP; e++) mx = fmaxf(mx, acc[e]);
    float p[N_EXP];
    float sum = 0.0f;
#pragma unroll
    for (int e = 0; e < N_EXP; e++) { p[e] = expf(acc[e] - mx); sum += p[e]; }
    float inv = 1.0f / sum;

    int i1 = 0; float v1 = p[0];
#pragma unroll
    for (int e = 1; e < N_EXP; e++) if (p[e] > v1) { v1 = p[e]; i1 = e; }
    int i2 = -1; float v2 = -1.0f;
#pragma unroll
    for (int e = 0; e < N_EXP; e++) if (e != i1 && p[e] > v2) { v2 = p[e]; i2 = e; }

    if (lane < N_EXP) {
        float g = (lane == i1) ? v1 * inv : (lane == i2) ? v2 * inv : 0.0f;
        g_gate[warp * N_EXP + lane] = g;
    }
}

// ---------------- unified mma.sync GEMM, virtual-K 3-stage pipeline ----------------
// Each virtual stage loads ONE (A,B) tile pair (20KB) into a 3-deep cp.async ring.
// MODE 0: grid.x = 10. bx<8 -> base tile: 96 stages cycling (Xhi,Whi),(Xlo,Whi),(Xhi,Wlo)
//                       per K-chunk; epilogue out = acc + bias.
//         bx>=8 -> LoRA tile: 32 stages (Xhi,Whi rows 1024+); epilogue g_H = bf16(acc*gate).
// MODE 1: grid.x = 8. delta: 8 stages (g_H, g_Bh), K=256; epilogue out += acc.
#define ROWB   80u          // 32 bf16 = 64B payload + 16B pad (conflict-free LDSM)
#define TILEB  (128u * ROWB)
#define SS     (2u * TILEB)       // stage stride (A tile + B tile)
#define SMEMSZ (3u * SS)          // 61440 B

template <int MODE>
__global__ void __launch_bounds__(256, 2)
mma_gemm(const float* __restrict__ bias, float* __restrict__ Cout) {
    extern __shared__ __align__(128) char smem[];
    const uint32_t sb = smem_u32(smem);
    const int tid  = threadIdx.x;
    const int lane = tid & 31;
    const int warp = tid >> 5;
    const int wm = warp >> 2;          // 0..1
    const int wn = warp & 3;           // 0..3
    const int m0 = blockIdx.y * 128;
    const int n0 = blockIdx.x * 128;

    const bool lora = (MODE == 0) && (blockIdx.x >= 8);
    const int  K    = (MODE == 0) ? 1024 : ER;
    const int  nst  = (MODE == 1) ? 8 : (lora ? 32 : 96);

    // per-thread cp.async slots: rows r0c, r0c+64 ; 16B-chunk k0c
    const int r0c = tid >> 2, k0c = tid & 3;

    // ---- stage loader: one (A,B) pair per virtual stage ----
    auto load_stage = [&](int buf, int s) {
        const __nv_bfloat16* __restrict__ Ap;
        const __nv_bfloat16* __restrict__ Bp;
        int k0;
        if (MODE == 1)      { Ap = g_H;   Bp = g_Bh;  k0 = s * 32; }
        else if (lora)      { Ap = g_Xhi; Bp = g_Whi; k0 = s * 32; }
        else {
            int q = s / 3, sub = s - 3 * q;
            k0 = q * 32;
            Ap = (sub == 1) ? g_Xlo : g_Xhi;
            Bp = (sub == 2) ? g_Wlo : g_Whi;
        }
        const size_t ge = (size_t)k0 + k0c * 8;
#pragma unroll
        for (int sr = 0; sr < 2; sr++) {
            int row = r0c + sr * 64;
            uint32_t so = (uint32_t)buf * SS + (uint32_t)row * ROWB + (uint32_t)k0c * 16;
            cp16(sb + so,         Ap + (size_t)(m0 + row) * K + ge);
            cp16(sb + TILEB + so, Bp + (size_t)(n0 + row) * K + ge);
        }
    };

    float acc[4][4][4];
#pragma unroll
    for (int a = 0; a < 4; a++)
#pragma unroll
        for (int b = 0; b < 4; b++)
#pragma unroll
            for (int c = 0; c < 4; c++) acc[a][b][c] = 0.0f;

    // ---- prologue: stages 0,1 ----
    load_stage(0, 0); CP_COMMIT();
    load_stage(1, 1); CP_COMMIT();

    const uint32_t arow = (uint32_t)(wm * 64 + (lane & 15));
    const uint32_t brow = (uint32_t)(wn * 32 + (lane & 15));

    int buf = 0;
    for (int i = 0; i < nst; i++) {
        CP_WAIT1();                 // stage i complete (≤1 group pending)
        __syncthreads();            // also: all warps done computing stage i-1

        if (i + 2 < nst) load_stage((buf + 2) % 3, i + 2);
        CP_COMMIT();

        const uint32_t sbase = sb + (uint32_t)buf * SS;
#pragma unroll
        for (int ks = 0; ks < 2; ks++) {
            const uint32_t kby = (uint32_t)(ks * 32 + (lane >> 4) * 16);
            uint32_t ah[4][4], bh[4][2];
#pragma unroll
            for (int mf = 0; mf < 4; mf++)
                ldsm4(ah[mf], sbase + (arow + mf * 16) * ROWB + kby);
#pragma unroll
            for (int p = 0; p < 2; p++) {
                uint32_t r[4];
                ldsm4(r, sbase + TILEB + (brow + p * 16) * ROWB + kby);
                bh[2 * p][0] = r[0]; bh[2 * p + 1][0] = r[1];
                bh[2 * p][1] = r[2]; bh[2 * p + 1][1] = r[3];
            }
#pragma unroll
            for (int mf = 0; mf < 4; mf++)
#pragma unroll
                for (int nf = 0; nf < 4; nf++)
                    mma_bf16(acc[mf][nf], ah[mf], bh[nf]);
        }
        buf = (buf + 1) % 3;
    }

    // ---------------- epilogue ----------------
    const int mr  = lane >> 2;
    const int nc2 = (lane & 3) * 2;
#pragma unroll
    for (int mf = 0; mf < 4; mf++) {
#pragma unroll
        for (int nf = 0; nf < 4; nf++) {
            const int m = m0 + wm * 64 + mf * 16 + mr;
            const int n = n0 + wn * 32 + nf * 8 + nc2;
            float* a = acc[mf][nf];
            if (MODE == 0 && !lora) {
                float2 bb = *(const float2*)(bias + n);
                float2 o0 = {a[0] + bb.x, a[1] + bb.y};
                float2 o1 = {a[2] + bb.x, a[3] + bb.y};
                *(float2*)(Cout + (size_t)m * D_OUT + n)       = o0;
                *(float2*)(Cout + (size_t)(m + 8) * D_OUT + n) = o1;
            } else if (MODE == 0) {
                const int er = n - D_OUT;
                const int ex = er >> 5;
                float gA = g_gate[m * N_EXP + ex];
                float gB = g_gate[(m + 8) * N_EXP + ex];
                *(__nv_bfloat162*)(g_H + (size_t)m * ER + er) =
                    __halves2bfloat162(__float2bfloat16_rn(a[0] * gA),
                                       __float2bfloat16_rn(a[1] * gA));
                *(__nv_bfloat162*)(g_H + (size_t)(m + 8) * ER + er) =
                    __halves2bfloat162(__float2bfloat16_rn(a[2] * gB),
                                       __float2bfloat16_rn(a[3] * gB));
            } else {
                float2 o0 = *(float2*)(Cout + (size_t)m * D_OUT + n);
                float2 o1 = *(float2*)(Cout + (size_t)(m + 8) * D_OUT + n);
                o0.x += a[0]; o0.y += a[1];
                o1.x += a[2]; o1.y += a[3];
                *(float2*)(Cout + (size_t)m * D_OUT + n)       = o0;
                *(float2*)(Cout + (size_t)(m + 8) * D_OUT + n) = o1;
            }
        }
    }
}

// ---------------- launcher ----------------
extern "C" void kernel_launch(void* const* d_in, const int* in_sizes, int n_in,
                              void* d_out, int out_size) {
    const float* x        = (const float*)d_in[0];
    const float* base_W   = (const float*)d_in[1];
    const float* base_b   = (const float*)d_in[2];
    const float* router_W = (const float*)d_in[3];
    const float* router_b = (const float*)d_in[4];
    const float* A        = (const float*)d_in[5];
    const float* S_a      = (const float*)d_in[6];
    const float* B        = (const float*)d_in[7];
    const float* S_b      = (const float*)d_in[8];
    float* out = (float*)d_out;

    cudaFuncSetAttribute((const void*)mma_gemm<0>,
                         cudaFuncAttributeMaxDynamicSharedMemorySize, SMEMSZ);
    cudaFuncSetAttribute((const void*)mma_gemm<1>,
                         cudaFuncAttributeMaxDynamicSharedMemorySize, SMEMSZ);

    // 1) weights -> bf16 (W hi/lo, Bcat hi)
    prep_kernel<<<1024, 512>>>(base_W, A, S_a, B, S_b);
    // 2) router (gates) + X -> bf16 hi/lo, fused
    router_kernel<<<T_TOK / 8, 256>>>((const float4*)x, (const float4*)router_W, router_b);
    // 3) fused base (3-pass virtual-K) + LoRA GEMM: out = X@W^T + b ; g_H = gate*(X@A_t^T)
    mma_gemm<0><<<dim3(10, 128), 256, SMEMSZ>>>(base_b, out);
    // 4) delta GEMM: out += g_H @ B_t^T
    mma_gemm<1><<<dim3(8, 128), 256, SMEMSZ>>>(nullptr, out);
}

// round 7
// speedup vs baseline: 1.1572x; 1.1572x over previous
#include <cuda_runtime.h>
#include <cuda_bf16.h>
#include <math.h>
#include <stdint.h>

// ---------------- problem constants ----------------
#define T_TOK 16384      // BATCH * SEQ
#define D_IN  1024
#define D_OUT 1024
#define N_EXP 8
#define RANK  32
#define ER    256        // N_EXP * RANK
#define NCAT  1280       // D_OUT + ER

// ---------------- device scratch (static; no allocations) ----------------
__device__ __nv_bfloat16 g_Whi[NCAT * D_IN];   // [W ; A*sig(S_a)] hi
__device__ __nv_bfloat16 g_Wlo[NCAT * D_IN];   // lo residual (base rows used; A rows unused)
__device__ __nv_bfloat16 g_Bh [D_OUT * ER];    // B*sig(S_b) bf16, [o][e*R+r]
__device__ __nv_bfloat16 g_Xhi[T_TOK * D_IN];
__device__ __nv_bfloat16 g_Xlo[T_TOK * D_IN];
__device__ __nv_bfloat16 g_H  [T_TOK * ER];    // gated low-rank activations (bf16)
__device__ float         g_gate[T_TOK * N_EXP];

// ---------------- PTX helpers (sm_80-baseline ISA only) ----------------
__device__ __forceinline__ uint32_t smem_u32(const void* p) {
    uint32_t a;
    asm("{ .reg .u64 t; cvta.to.shared.u64 t, %1; cvt.u32.u64 %0, t; }"
        : "=r"(a) : "l"(p));
    return a;
}

__device__ __forceinline__ void cp16(uint32_t s, const void* g) {
    asm volatile("cp.async.cg.shared.global [%0], [%1], 16;" :: "r"(s), "l"(g) : "memory");
}
#define CP_COMMIT() asm volatile("cp.async.commit_group;" ::: "memory")
#define CP_WAIT1()  asm volatile("cp.async.wait_group 1;" ::: "memory")

__device__ __forceinline__ void ldsm4(uint32_t* r, uint32_t addr) {
    asm volatile("ldmatrix.sync.aligned.m8n8.x4.shared.b16 {%0,%1,%2,%3}, [%4];"
                 : "=r"(r[0]), "=r"(r[1]), "=r"(r[2]), "=r"(r[3]) : "r"(addr));
}

__device__ __forceinline__ void mma_bf16(float* c, const uint32_t* a, const uint32_t* b) {
    asm volatile(
        "mma.sync.aligned.m16n8k16.row.col.f32.bf16.bf16.f32 "
        "{%0,%1,%2,%3}, {%4,%5,%6,%7}, {%8,%9}, {%0,%1,%2,%3};"
        : "+f"(c[0]), "+f"(c[1]), "+f"(c[2]), "+f"(c[3])
        : "r"(a[0]), "r"(a[1]), "r"(a[2]), "r"(a[3]), "r"(b[0]), "r"(b[1]));
}

// ---------------- prep: weights -> bf16 (hi/lo for W, hi for Bcat) ----------------
__global__ void prep_kernel(const float* __restrict__ base_W,
                            const float* __restrict__ A,
                            const float* __restrict__ S_a,
                            const float* __restrict__ B,
                            const float* __restrict__ S_b) {
    const int totalW = D_OUT * D_IN;           // 1048576
    const int totalA = ER * D_IN;              // 262144
    const int totalB = N_EXP * D_OUT * RANK;   // 262144
    const int total  = totalW + totalA + totalB;
    for (int idx = blockIdx.x * blockDim.x + threadIdx.x; idx < total;
         idx += gridDim.x * blockDim.x) {
        if (idx < totalW) {
            float v = base_W[idx];
            __nv_bfloat16 h = __float2bfloat16_rn(v);
            g_Whi[idx] = h;
            g_Wlo[idx] = __float2bfloat16_rn(v - __bfloat162float(h));
        } else if (idx < totalW + totalA) {
            int i = idx - totalW;              // A is [E,R,D_IN]: row (e*R+r), col d
            float s = S_a[i];
            float v = A[i] * (1.0f / (1.0f + expf(-s)));
            __nv_bfloat16 h = __float2bfloat16_rn(v);
            g_Whi[totalW + i] = h;
            g_Wlo[totalW + i] = __float2bfloat16_rn(v - __bfloat162float(h));
        } else {
            int i = idx - totalW - totalA;     // B is [E, D_OUT, R]
            int e   = i / (D_OUT * RANK);
            int rem = i - e * (D_OUT * RANK);
            int o   = rem / RANK;
            int r   = rem - o * RANK;
            float s = S_b[i];
            float v = B[i] * (1.0f / (1.0f + expf(-s)));
            g_Bh[o * ER + e * RANK + r] = __float2bfloat16_rn(v);
        }
    }
}

// ---------------- router + X conversion fused ----------------
__global__ void router_kernel(const float4* __restrict__ x4,
                              const float4* __restrict__ rw4,
                              const float* __restrict__ router_b) {
    const int warp = (blockIdx.x * blockDim.x + threadIdx.x) >> 5;
    const int lane = threadIdx.x & 31;
    if (warp >= T_TOK) return;

    float acc[N_EXP];
#pragma unroll
    for (int e = 0; e < N_EXP; e++) acc[e] = 0.0f;

    const float4* xrow = x4 + (size_t)warp * (D_IN / 4);
    __nv_bfloat162* xh2 = (__nv_bfloat162*)(g_Xhi + (size_t)warp * D_IN);
    __nv_bfloat162* xl2 = (__nv_bfloat162*)(g_Xlo + (size_t)warp * D_IN);
#pragma unroll 2
    for (int j = lane; j < D_IN / 4; j += 32) {
        float4 xv = xrow[j];
#pragma unroll
        for (int e = 0; e < N_EXP; e++) {
            float4 wv = rw4[e * (D_IN / 4) + j];
            acc[e] += xv.x * wv.x + xv.y * wv.y + xv.z * wv.z + xv.w * wv.w;
        }
        __nv_bfloat16 h0 = __float2bfloat16_rn(xv.x);
        __nv_bfloat16 h1 = __float2bfloat16_rn(xv.y);
        __nv_bfloat16 h2 = __float2bfloat16_rn(xv.z);
        __nv_bfloat16 h3 = __float2bfloat16_rn(xv.w);
        xh2[2 * j]     = __halves2bfloat162(h0, h1);
        xh2[2 * j + 1] = __halves2bfloat162(h2, h3);
        xl2[2 * j]     = __halves2bfloat162(
            __float2bfloat16_rn(xv.x - __bfloat162float(h0)),
            __float2bfloat16_rn(xv.y - __bfloat162float(h1)));
        xl2[2 * j + 1] = __halves2bfloat162(
            __float2bfloat16_rn(xv.z - __bfloat162float(h2)),
            __float2bfloat16_rn(xv.w - __bfloat162float(h3)));
    }
#pragma unroll
    for (int e = 0; e < N_EXP; e++) {
#pragma unroll
        for (int off = 16; off; off >>= 1)
            acc[e] += __shfl_xor_sync(0xffffffffu, acc[e], off);
        acc[e] += router_b[e];
    }

    float mx = acc[0];
#pragma unroll
    for (int e = 1; e < N_EXP; e++) mx = fmaxf(mx, acc[e]);
    float p[N_EXP];
    float sum = 0.0f;
#pragma unroll
    for (int e = 0; e < N_EXP; e++) { p[e] = expf(acc[e] - mx); sum += p[e]; }
    float inv = 1.0f / sum;

    int i1 = 0; float v1 = p[0];
#pragma unroll
    for (int e = 1; e < N_EXP; e++) if (p[e] > v1) { v1 = p[e]; i1 = e; }
    int i2 = -1; float v2 = -1.0f;
#pragma unroll
    for (int e = 0; e < N_EXP; e++) if (e != i1 && p[e] > v2) { v2 = p[e]; i2 = e; }

    if (lane < N_EXP) {
        float g = (lane == i1) ? v1 * inv : (lane == i2) ? v2 * inv : 0.0f;
        g_gate[warp * N_EXP + lane] = g;
    }
}

// ---------------- mma.sync GEMM (R4 structure + delta fusion) ----------------
// MODE 1 (runs FIRST): LoRA GEMM. A=Xhi, B=Whi rows 1024+, K=1024, 32 stages,
//                      single-pass. Epilogue: g_H = bf16(gate * acc).
// MODE 0 (runs SECOND): fused base+delta. Stages 0..31: 3-pass hi/lo X@W^T
//                      (loads Ah,Al,Bh,Bl per 32-K chunk). Stages 32..39:
//                      single-pass H@Bh^T (K=256) into the SAME accumulators.
//                      Epilogue: out = acc + bias (single store, no RMW).
#define ROWB  80u          // 32 bf16 = 64B payload + 16B pad (conflict-free LDSM)
#define TILEB (128u * ROWB)
#define OFF_AL (TILEB)
#define OFF_BH (2u * TILEB)
#define OFF_BL (3u * TILEB)
#define SS     (4u * TILEB)      // stage stride (4 tile slots)
#define SMEMSZ (2u * SS)         // 81920 B double buffer

template <int MODE>
__global__ void __launch_bounds__(256)
mma_gemm(const float* __restrict__ bias, float* __restrict__ Cout) {
    constexpr int NST = (MODE == 0) ? 40 : 32;

    extern __shared__ __align__(128) char smem[];
    const uint32_t sb = smem_u32(smem);
    const int tid  = threadIdx.x;
    const int lane = tid & 31;
    const int warp = tid >> 5;
    const int wm = warp >> 2;          // 0..1
    const int wn = warp & 3;           // 0..3
    const int m0 = blockIdx.y * 128;
    const int n0 = blockIdx.x * 128 + ((MODE == 1) ? D_OUT : 0);

    // per-thread cp.async slots: rows r0c, r0c+64 ; 16B-chunk k0c
    const int r0c = tid >> 2, k0c = tid & 3;

    // ---- stage loader ----
    auto load_stage = [&](int stg, int s) {
        const uint32_t sbase = (uint32_t)stg * SS;
        if (MODE == 0 && s >= 32) {
            // delta stage: A = g_H [T,ER], B = g_Bh [D_OUT,ER], K=256
            const size_t ge = (size_t)(s - 32) * 32 + k0c * 8;
#pragma unroll
            for (int sr = 0; sr < 2; sr++) {
                int row = r0c + sr * 64;
                uint32_t so = sbase + (uint32_t)row * ROWB + (uint32_t)k0c * 16;
                cp16(sb + so,          g_H  + (size_t)(m0 + row) * ER + ge);
                cp16(sb + OFF_BH + so, g_Bh + (size_t)(n0 + row) * ER + ge);
            }
        } else {
            const size_t ge = (size_t)s * 32 + k0c * 8;
#pragma unroll
            for (int sr = 0; sr < 2; sr++) {
                int row = r0c + sr * 64;
                uint32_t so = sbase + (uint32_t)row * ROWB + (uint32_t)k0c * 16;
                cp16(sb + so,          g_Xhi + (size_t)(m0 + row) * D_IN + ge);
                cp16(sb + OFF_BH + so, g_Whi + (size_t)(n0 + row) * D_IN + ge);
                if (MODE == 0) {
                    cp16(sb + OFF_AL + so, g_Xlo + (size_t)(m0 + row) * D_IN + ge);
                    cp16(sb + OFF_BL + so, g_Wlo + (size_t)(n0 + row) * D_IN + ge);
                }
            }
        }
    };

    float acc[4][4][4];
#pragma unroll
    for (int a = 0; a < 4; a++)
#pragma unroll
        for (int b = 0; b < 4; b++)
#pragma unroll
            for (int c = 0; c < 4; c++) acc[a][b][c] = 0.0f;

    load_stage(0, 0);
    CP_COMMIT();

    const uint32_t arow = (uint32_t)(wm * 64 + (lane & 15));
    const uint32_t brow = (uint32_t)(wn * 32 + (lane & 15));

    int buf = 0;
    for (int s = 0; s < NST; s++) {
        if (s + 1 < NST) load_stage(buf ^ 1, s + 1);
        CP_COMMIT();
        CP_WAIT1();
        __syncthreads();

        const bool three = (MODE == 0) && (s < 32);
        const uint32_t sbase = sb + (uint32_t)buf * SS;
#pragma unroll
        for (int ks = 0; ks < 2; ks++) {
            const uint32_t kby = (uint32_t)(ks * 32 + (lane >> 4) * 16);
            uint32_t ah[4][4], bh[4][2];
#pragma unroll
            for (int mf = 0; mf < 4; mf++)
                ldsm4(ah[mf], sbase + (arow + mf * 16) * ROWB + kby);
#pragma unroll
            for (int p = 0; p < 2; p++) {
                uint32_t r[4];
                ldsm4(r, sbase + OFF_BH + (brow + p * 16) * ROWB + kby);
                bh[2 * p][0] = r[0]; bh[2 * p + 1][0] = r[1];
                bh[2 * p][1] = r[2]; bh[2 * p + 1][1] = r[3];
            }
#pragma unroll
            for (int mf = 0; mf < 4; mf++)
#pragma unroll
                for (int nf = 0; nf < 4; nf++)
                    mma_bf16(acc[mf][nf], ah[mf], bh[nf]);

            if (three) {
                uint32_t al[4][4], bl[4][2];
#pragma unroll
                for (int mf = 0; mf < 4; mf++)
                    ldsm4(al[mf], sbase + OFF_AL + (arow + mf * 16) * ROWB + kby);
#pragma unroll
                for (int p = 0; p < 2; p++) {
                    uint32_t r[4];
                    ldsm4(r, sbase + OFF_BL + (brow + p * 16) * ROWB + kby);
                    bl[2 * p][0] = r[0]; bl[2 * p + 1][0] = r[1];
                    bl[2 * p][1] = r[2]; bl[2 * p + 1][1] = r[3];
                }
#pragma unroll
                for (int mf = 0; mf < 4; mf++)
#pragma unroll
                    for (int nf = 0; nf < 4; nf++) {
                        mma_bf16(acc[mf][nf], al[mf], bh[nf]);
                        mma_bf16(acc[mf][nf], ah[mf], bl[nf]);
                    }
            }
        }
        __syncthreads();
        buf ^= 1;
    }

    // ---------------- epilogue ----------------
    const int mr  = lane >> 2;
    const int nc2 = (lane & 3) * 2;
#pragma unroll
    for (int mf = 0; mf < 4; mf++) {
#pragma unroll
        for (int nf = 0; nf < 4; nf++) {
            const int m = m0 + wm * 64 + mf * 16 + mr;
            const int n = n0 + wn * 32 + nf * 8 + nc2;
            float* a = acc[mf][nf];
            if (MODE == 0) {
                float2 bb = *(const float2*)(bias + n);
                float2 o0 = {a[0] + bb.x, a[1] + bb.y};
                float2 o1 = {a[2] + bb.x, a[3] + bb.y};
                *(float2*)(Cout + (size_t)m * D_OUT + n)       = o0;
                *(float2*)(Cout + (size_t)(m + 8) * D_OUT + n) = o1;
            } else {
                const int er = n - D_OUT;
                const int ex = er >> 5;
                float gA = g_gate[m * N_EXP + ex];
                float gB = g_gate[(m + 8) * N_EXP + ex];
                *(__nv_bfloat162*)(g_H + (size_t)m * ER + er) =
                    __halves2bfloat162(__float2bfloat16_rn(a[0] * gA),
                                       __float2bfloat16_rn(a[1] * gA));
                *(__nv_bfloat162*)(g_H + (size_t)(m + 8) * ER + er) =
                    __halves2bfloat162(__float2bfloat16_rn(a[2] * gB),
                                       __float2bfloat16_rn(a[3] * gB));
            }
        }
    }
}

// ---------------- launcher ----------------
extern "C" void kernel_launch(void* const* d_in, const int* in_sizes, int n_in,
                              void* d_out, int out_size) {
    const float* x        = (const float*)d_in[0];
    const float* base_W   = (const float*)d_in[1];
    const float* base_b   = (const float*)d_in[2];
    const float* router_W = (const float*)d_in[3];
    const float* router_b = (const float*)d_in[4];
    const float* A        = (const float*)d_in[5];
    const float* S_a      = (const float*)d_in[6];
    const float* B        = (const float*)d_in[7];
    const float* S_b      = (const float*)d_in[8];
    float* out = (float*)d_out;

    cudaFuncSetAttribute((const void*)mma_gemm<0>,
                         cudaFuncAttributeMaxDynamicSharedMemorySize, SMEMSZ);
    cudaFuncSetAttribute((const void*)mma_gemm<1>,
                         cudaFuncAttributeMaxDynamicSharedMemorySize, SMEMSZ);

    // 1) weights -> bf16 (W hi/lo, Bcat hi)
    prep_kernel<<<1024, 512>>>(base_W, A, S_a, B, S_b);
    // 2) router (gates) + X -> bf16 hi/lo, fused
    router_kernel<<<T_TOK / 8, 256>>>((const float4*)x, (const float4*)router_W, router_b);
    // 3) LoRA GEMM first: g_H = gate * (X @ A_t^T)
    mma_gemm<1><<<dim3(2, 128), 256, SMEMSZ>>>(nullptr, out);
    // 4) fused base+delta: out = X@W^T (3-pass) + g_H@B_t^T + bias  (single store)
    mma_gemm<0><<<dim3(8, 128), 256, SMEMSZ>>>(base_b, out);
}

// round 10
// speedup vs baseline: 1.3126x; 1.1343x over previous
#include <cuda_runtime.h>
#include <cuda_bf16.h>
#include <math.h>
#include <stdint.h>

// ---------------- problem constants ----------------
#define T_TOK 16384      // BATCH * SEQ
#define D_IN  1024
#define D_OUT 1024
#define N_EXP 8
#define RANK  32
#define ER    256        // N_EXP * RANK
#define NCAT  1280       // D_OUT + ER

// ---------------- device scratch (static; no allocations) ----------------
__device__ __nv_bfloat16 g_Whi[NCAT * D_IN];   // [W ; A*sig(S_a)] hi
__device__ __nv_bfloat16 g_Wlo[NCAT * D_IN];   // lo residual (base rows used; A rows unused)
__device__ __nv_bfloat16 g_Bh [D_OUT * ER];    // B*sig(S_b) bf16, [o][e*R+r]
__device__ __nv_bfloat16 g_Xhi[T_TOK * D_IN];
__device__ __nv_bfloat16 g_Xlo[T_TOK * D_IN];
__device__ __nv_bfloat16 g_H  [T_TOK * ER];    // gated low-rank activations (bf16)
__device__ float         g_gate[T_TOK * N_EXP];

// ---------------- PTX helpers (sm_80-baseline ISA only) ----------------
__device__ __forceinline__ uint32_t smem_u32(const void* p) {
    uint32_t a;
    asm("{ .reg .u64 t; cvta.to.shared.u64 t, %1; cvt.u32.u64 %0, t; }"
        : "=r"(a) : "l"(p));
    return a;
}

__device__ __forceinline__ void cp16(uint32_t s, const void* g) {
    asm volatile("cp.async.cg.shared.global [%0], [%1], 16;" :: "r"(s), "l"(g) : "memory");
}
#define CP_COMMIT() asm volatile("cp.async.commit_group;" ::: "memory")
#define CP_WAIT1()  asm volatile("cp.async.wait_group 1;" ::: "memory")

__device__ __forceinline__ void ldsm4(uint32_t* r, uint32_t addr) {
    asm volatile("ldmatrix.sync.aligned.m8n8.x4.shared.b16 {%0,%1,%2,%3}, [%4];"
                 : "=r"(r[0]), "=r"(r[1]), "=r"(r[2]), "=r"(r[3]) : "r"(addr));
}

__device__ __forceinline__ void mma_bf16(float* c, const uint32_t* a, const uint32_t* b) {
    asm volatile(
        "mma.sync.aligned.m16n8k16.row.col.f32.bf16.bf16.f32 "
        "{%0,%1,%2,%3}, {%4,%5,%6,%7}, {%8,%9}, {%0,%1,%2,%3};"
        : "+f"(c[0]), "+f"(c[1]), "+f"(c[2]), "+f"(c[3])
        : "r"(a[0]), "r"(a[1]), "r"(a[2]), "r"(a[3]), "r"(b[0]), "r"(b[1]));
}

// ---------------- prep: weights -> bf16 (hi/lo for W, hi for Bcat) ----------------
__global__ void prep_kernel(const float* __restrict__ base_W,
                            const float* __restrict__ A,
                            const float* __restrict__ S_a,
                            const float* __restrict__ B,
                            const float* __restrict__ S_b) {
    const int totalW = D_OUT * D_IN;           // 1048576
    const int totalA = ER * D_IN;              // 262144
    const int totalB = N_EXP * D_OUT * RANK;   // 262144
    const int total  = totalW + totalA + totalB;
    for (int idx = blockIdx.x * blockDim.x + threadIdx.x; idx < total;
         idx += gridDim.x * blockDim.x) {
        if (idx < totalW) {
            float v = base_W[idx];
            __nv_bfloat16 h = __float2bfloat16_rn(v);
            g_Whi[idx] = h;
            g_Wlo[idx] = __float2bfloat16_rn(v - __bfloat162float(h));
        } else if (idx < totalW + totalA) {
            int i = idx - totalW;              // A is [E,R,D_IN]: row (e*R+r), col d
            float s = S_a[i];
            float v = A[i] * (1.0f / (1.0f + expf(-s)));
            __nv_bfloat16 h = __float2bfloat16_rn(v);
            g_Whi[totalW + i] = h;
            g_Wlo[totalW + i] = __float2bfloat16_rn(v - __bfloat162float(h));
        } else {
            int i = idx - totalW - totalA;     // B is [E, D_OUT, R]
            int e   = i / (D_OUT * RANK);
            int rem = i - e * (D_OUT * RANK);
            int o   = rem / RANK;
            int r   = rem - o * RANK;
            float s = S_b[i];
            float v = B[i] * (1.0f / (1.0f + expf(-s)));
            g_Bh[o * ER + e * RANK + r] = __float2bfloat16_rn(v);
        }
    }
}

// ---------------- router + X conversion fused ----------------
__global__ void router_kernel(const float4* __restrict__ x4,
                              const float4* __restrict__ rw4,
                              const float* __restrict__ router_b) {
    const int warp = (blockIdx.x * blockDim.x + threadIdx.x) >> 5;
    const int lane = threadIdx.x & 31;
    if (warp >= T_TOK) return;

    float acc[N_EXP];
#pragma unroll
    for (int e = 0; e < N_EXP; e++) acc[e] = 0.0f;

    const float4* xrow = x4 + (size_t)warp * (D_IN / 4);
    __nv_bfloat162* xh2 = (__nv_bfloat162*)(g_Xhi + (size_t)warp * D_IN);
    __nv_bfloat162* xl2 = (__nv_bfloat162*)(g_Xlo + (size_t)warp * D_IN);
#pragma unroll 2
    for (int j = lane; j < D_IN / 4; j += 32) {
        float4 xv = xrow[j];
#pragma unroll
        for (int e = 0; e < N_EXP; e++) {
            float4 wv = rw4[e * (D_IN / 4) + j];
            acc[e] += xv.x * wv.x + xv.y * wv.y + xv.z * wv.z + xv.w * wv.w;
        }
        __nv_bfloat16 h0 = __float2bfloat16_rn(xv.x);
        __nv_bfloat16 h1 = __float2bfloat16_rn(xv.y);
        __nv_bfloat16 h2 = __float2bfloat16_rn(xv.z);
        __nv_bfloat16 h3 = __float2bfloat16_rn(xv.w);
        xh2[2 * j]     = __halves2bfloat162(h0, h1);
        xh2[2 * j + 1] = __halves2bfloat162(h2, h3);
        xl2[2 * j]     = __halves2bfloat162(
            __float2bfloat16_rn(xv.x - __bfloat162float(h0)),
            __float2bfloat16_rn(xv.y - __bfloat162float(h1)));
        xl2[2 * j + 1] = __halves2bfloat162(
            __float2bfloat16_rn(xv.z - __bfloat162float(h2)),
            __float2bfloat16_rn(xv.w - __bfloat162float(h3)));
    }
#pragma unroll
    for (int e = 0; e < N_EXP; e++) {
#pragma unroll
        for (int off = 16; off; off >>= 1)
            acc[e] += __shfl_xor_sync(0xffffffffu, acc[e], off);
        acc[e] += router_b[e];
    }

    float mx = acc[0];
#pragma unroll
    for (int e = 1; e < N_EXP; e++) mx = fmaxf(mx, acc[e]);
    float p[N_EXP];
    float sum = 0.0f;
#pragma unroll
    for (int e = 0; e < N_EXP; e++) { p[e] = expf(acc[e] - mx); sum += p[e]; }
    float inv = 1.0f / sum;

    int i1 = 0; float v1 = p[0];
#pragma unroll
    for (int e = 1; e < N_EXP; e++) if (p[e] > v1) { v1 = p[e]; i1 = e; }
    int i2 = -1; float v2 = -1.0f;
#pragma unroll
    for (int e = 0; e < N_EXP; e++) if (e != i1 && p[e] > v2) { v2 = p[e]; i2 = e; }

    if (lane < N_EXP) {
        float g = (lane == i1) ? v1 * inv : (lane == i2) ? v2 * inv : 0.0f;
        g_gate[warp * N_EXP + lane] = g;
    }
}

// ---------------- mma.sync GEMM (R7 structure, XOR-swizzled 64B rows) ----------------
// Tile rows are 64B (32 bf16); 16B chunk c of row r stored at
//   r*64 + ((c ^ ((r>>1)&3)) * 16)
// -> cp.async stores and every ldmatrix phase are bank-conflict-free, and the
//    XOR term is a lane constant in the compute loop (fragment offsets +16/+64
//    rows don't touch row bits 1-2).
// Stage = 4 tiles * 8KB = 32KB; double buffer 64KB -> 2 CTAs/SM.
// MODE 1 (runs FIRST): LoRA GEMM (single-pass, 32 stages): g_H = bf16(gate*acc).
// MODE 0 (runs SECOND): fused base+delta: 32 heavy stages (3-pass hi/lo X@W^T)
//                      + 8 light stages (H@Bh^T), single-store epilogue.
#define TILEB  8192u            // 128 rows * 64 B
#define OFF_AL (TILEB)
#define OFF_BH (2u * TILEB)
#define OFF_BL (3u * TILEB)
#define SS     (4u * TILEB)     // stage stride
#define SMEMSZ (2u * SS)        // 65536 B double buffer

template <int MODE>
__global__ void __launch_bounds__(256, 2)
mma_gemm(const float* __restrict__ bias, float* __restrict__ Cout) {
    constexpr int NST = (MODE == 0) ? 40 : 32;

    extern __shared__ __align__(128) char smem[];
    const uint32_t sb = smem_u32(smem);
    const int tid  = threadIdx.x;
    const int lane = tid & 31;
    const int warp = tid >> 5;
    const int wm = warp >> 2;          // 0..1
    const int wn = warp & 3;           // 0..3
    const int m0 = blockIdx.y * 128;
    const int n0 = blockIdx.x * 128 + ((MODE == 1) ? D_OUT : 0);

    // cp.async mapping: thread -> row r0c (+64), chunk k0c; swizzled store slot
    const int r0c = tid >> 2, k0c = tid & 3;
    const uint32_t stso = (uint32_t)r0c * 64 +
                          (uint32_t)((k0c ^ ((r0c >> 1) & 3)) * 16);  // valid for row+64 too

    // ---- stage loader ----
    auto load_stage = [&](int stg, int s) {
        const uint32_t sbase = (uint32_t)stg * SS;
        if (MODE == 0 && s >= 32) {
            // delta stage: A = g_H [T,ER], B = g_Bh [D_OUT,ER], K=256
            const size_t ge = (size_t)(s - 32) * 32 + k0c * 8;
#pragma unroll
            for (int sr = 0; sr < 2; sr++) {
                uint32_t so = sbase + stso + sr * 4096u;
                int row = r0c + sr * 64;
                cp16(sb + so,          g_H  + (size_t)(m0 + row) * ER + ge);
                cp16(sb + OFF_BH + so, g_Bh + (size_t)(n0 + row) * ER + ge);
            }
        } else {
            const size_t ge = (size_t)s * 32 + k0c * 8;
#pragma unroll
            for (int sr = 0; sr < 2; sr++) {
                uint32_t so = sbase + stso + sr * 4096u;
                int row = r0c + sr * 64;
                cp16(sb + so,          g_Xhi + (size_t)(m0 + row) * D_IN + ge);
                cp16(sb + OFF_BH + so, g_Whi + (size_t)(n0 + row) * D_IN + ge);
                if (MODE == 0) {
                    cp16(sb + OFF_AL + so, g_Xlo + (size_t)(m0 + row) * D_IN + ge);
                    cp16(sb + OFF_BL + so, g_Wlo + (size_t)(n0 + row) * D_IN + ge);
                }
            }
        }
    };

    float acc[4][4][4];
#pragma unroll
    for (int a = 0; a < 4; a++)
#pragma unroll
        for (int b = 0; b < 4; b++)
#pragma unroll
            for (int c = 0; c < 4; c++) acc[a][b][c] = 0.0f;

    load_stage(0, 0);
    CP_COMMIT();

    // compute-side addressing (row*64 + swizzled-chunk*16)
    const uint32_t arow = (uint32_t)(wm * 64 + (lane & 15));
    const uint32_t brow = (uint32_t)(wn * 32 + (lane & 15));
    const uint32_t kxor = (uint32_t)((lane >> 1) & 3);   // row bits 1-2 of (lane&15)

    int buf = 0;
    for (int s = 0; s < NST; s++) {
        if (s + 1 < NST) load_stage(buf ^ 1, s + 1);
        CP_COMMIT();
        CP_WAIT1();
        __syncthreads();

        const bool three = (MODE == 0) && (s < 32);
        const uint32_t sbase = sb + (uint32_t)buf * SS;
#pragma unroll
        for (int ks = 0; ks < 2; ks++) {
            const uint32_t kb = (((uint32_t)(ks * 2) + (lane >> 4)) ^ kxor) * 16;
            uint32_t ah[4][4], bh[4][2];
#pragma unroll
            for (int mf = 0; mf < 4; mf++)
                ldsm4(ah[mf], sbase + (arow + mf * 16) * 64 + kb);
#pragma unroll
            for (int p = 0; p < 2; p++) {
                uint32_t r[4];
                ldsm4(r, sbase + OFF_BH + (brow + p * 16) * 64 + kb);
                bh[2 * p][0] = r[0]; bh[2 * p + 1][0] = r[1];
                bh[2 * p][1] = r[2]; bh[2 * p + 1][1] = r[3];
            }
#pragma unroll
            for (int mf = 0; mf < 4; mf++)
#pragma unroll
                for (int nf = 0; nf < 4; nf++)
                    mma_bf16(acc[mf][nf], ah[mf], bh[nf]);

            if (three) {
                uint32_t al[4][4], bl[4][2];
#pragma unroll
                for (int mf = 0; mf < 4; mf++)
                    ldsm4(al[mf], sbase + OFF_AL + (arow + mf * 16) * 64 + kb);
#pragma unroll
                for (int p = 0; p < 2; p++) {
                    uint32_t r[4];
                    ldsm4(r, sbase + OFF_BL + (brow + p * 16) * 64 + kb);
                    bl[2 * p][0] = r[0]; bl[2 * p + 1][0] = r[1];
                    bl[2 * p][1] = r[2]; bl[2 * p + 1][1] = r[3];
                }
#pragma unroll
                for (int mf = 0; mf < 4; mf++)
#pragma unroll
                    for (int nf = 0; nf < 4; nf++) {
                        mma_bf16(acc[mf][nf], al[mf], bh[nf]);
                        mma_bf16(acc[mf][nf], ah[mf], bl[nf]);
                    }
            }
        }
        __syncthreads();
        buf ^= 1;
    }

    // ---------------- epilogue ----------------
    const int mr  = lane >> 2;
    const int nc2 = (lane & 3) * 2;
#pragma unroll
    for (int mf = 0; mf < 4; mf++) {
#pragma unroll
        for (int nf = 0; nf < 4; nf++) {
            const int m = m0 + wm * 64 + mf * 16 + mr;
            const int n = n0 + wn * 32 + nf * 8 + nc2;
            float* a = acc[mf][nf];
            if (MODE == 0) {
                float2 bb = *(const float2*)(bias + n);
                float2 o0 = {a[0] + bb.x, a[1] + bb.y};
                float2 o1 = {a[2] + bb.x, a[3] + bb.y};
                *(float2*)(Cout + (size_t)m * D_OUT + n)       = o0;
                *(float2*)(Cout + (size_t)(m + 8) * D_OUT + n) = o1;
            } else {
                const int er = n - D_OUT;
                const int ex = er >> 5;
                float gA = g_gate[m * N_EXP + ex];
                float gB = g_gate[(m + 8) * N_EXP + ex];
                *(__nv_bfloat162*)(g_H + (size_t)m * ER + er) =
                    __halves2bfloat162(__float2bfloat16_rn(a[0] * gA),
                                       __float2bfloat16_rn(a[1] * gA));
                *(__nv_bfloat162*)(g_H + (size_t)(m + 8) * ER + er) =
                    __halves2bfloat162(__float2bfloat16_rn(a[2] * gB),
                                       __float2bfloat16_rn(a[3] * gB));
            }
        }
    }
}

// ---------------- launcher ----------------
extern "C" void kernel_launch(void* const* d_in, const int* in_sizes, int n_in,
                              void* d_out, int out_size) {
    const float* x        = (const float*)d_in[0];
    const float* base_W   = (const float*)d_in[1];
    const float* base_b   = (const float*)d_in[2];
    const float* router_W = (const float*)d_in[3];
    const float* router_b = (const float*)d_in[4];
    const float* A        = (const float*)d_in[5];
    const float* S_a      = (const float*)d_in[6];
    const float* B        = (const float*)d_in[7];
    const float* S_b      = (const float*)d_in[8];
    float* out = (float*)d_out;

    cudaFuncSetAttribute((const void*)mma_gemm<0>,
                         cudaFuncAttributeMaxDynamicSharedMemorySize, SMEMSZ);
    cudaFuncSetAttribute((const void*)mma_gemm<1>,
                         cudaFuncAttributeMaxDynamicSharedMemorySize, SMEMSZ);

    // 1) weights -> bf16 (W hi/lo, Bcat hi)
    prep_kernel<<<1024, 512>>>(base_W, A, S_a, B, S_b);
    // 2) router (gates) + X -> bf16 hi/lo, fused
    router_kernel<<<T_TOK / 8, 256>>>((const float4*)x, (const float4*)router_W, router_b);
    // 3) LoRA GEMM first: g_H = gate * (X @ A_t^T)
    mma_gemm<1><<<dim3(2, 128), 256, SMEMSZ>>>(nullptr, out);
    // 4) fused base+delta: out = X@W^T (3-pass) + g_H@B_t^T + bias  (single store)
    mma_gemm<0><<<dim3(8, 128), 256, SMEMSZ>>>(base_b, out);
}